// round 8
// baseline (speedup 1.0000x reference)
#include <cuda_runtime.h>

#define EPS 1e-4f
#define FRAMES 4000
#define NF4 1000            // 4000 floats = 1000 float4
#define T 256               // each thread owns 4 consecutive float4 = 16 elems

__global__ __launch_bounds__(T) void cumnorm_kernel(const float4* __restrict__ x,
                                                    float4* __restrict__ out) {
    __shared__ float wsum1[8];
    __shared__ float wsum2[8];

    const int tid = threadIdx.x;
    const long long rowbase = (long long)blockIdx.x * NF4;
    const int b4 = 4 * tid;                 // first float4 index of this chunk

    // 1) direct gmem -> regs: 4 consecutive float4 per thread (64B contiguous,
    //    warp covers 2KB contiguous => 100% sector utilization), MLP=4.
    float4 v[4];
    float s1 = 0.f, s2 = 0.f;
#pragma unroll
    for (int j = 0; j < 4; j++) {
        float4 a = make_float4(0.f, 0.f, 0.f, 0.f);
        if (b4 + j < NF4) a = __ldcs(&x[rowbase + b4 + j]);
        v[j] = a;
        s1 += a.x + a.y + a.z + a.w;
        s2 = fmaf(a.x, a.x, s2); s2 = fmaf(a.y, a.y, s2);
        s2 = fmaf(a.z, a.z, s2); s2 = fmaf(a.w, a.w, s2);
    }

    // 2) block-wide exclusive scan of (s1, s2)
    const int lane = tid & 31;
    const int wid = tid >> 5;
    float i1 = s1, i2 = s2;
#pragma unroll
    for (int o = 1; o < 32; o <<= 1) {
        float t1 = __shfl_up_sync(0xffffffffu, i1, o);
        float t2 = __shfl_up_sync(0xffffffffu, i2, o);
        if (lane >= o) { i1 += t1; i2 += t2; }
    }
    if (lane == 31) { wsum1[wid] = i1; wsum2[wid] = i2; }
    __syncthreads();

    float w1 = 0.f, w2 = 0.f;
#pragma unroll
    for (int w = 0; w < 8; w++) {
        if (w < wid) { w1 += wsum1[w]; w2 += wsum2[w]; }
    }
    float r1 = w1 + (i1 - s1);   // exclusive prefix sums for this chunk
    float r2 = w2 + (i2 - s2);

    // 3) causal normalization, division-free:
    //    (x - r1/c) / sqrt(r2/c - (r1/c)^2 + eps)
    //  = (c*x - r1) * rsqrt(c*r2 - r1^2 + eps*c^2)
    float c = (float)(16 * tid);
#pragma unroll
    for (int j = 0; j < 4; j++) {
        float4 a = v[j];
        float4 o;
        {
            c += 1.f; r1 += a.x; r2 = fmaf(a.x, a.x, r2);
            float S = fmaf(EPS * c, c, fmaf(c, r2, -r1 * r1));
            o.x = fmaf(c, a.x, -r1) * rsqrtf(S);
        }
        {
            c += 1.f; r1 += a.y; r2 = fmaf(a.y, a.y, r2);
            float S = fmaf(EPS * c, c, fmaf(c, r2, -r1 * r1));
            o.y = fmaf(c, a.y, -r1) * rsqrtf(S);
        }
        {
            c += 1.f; r1 += a.z; r2 = fmaf(a.z, a.z, r2);
            float S = fmaf(EPS * c, c, fmaf(c, r2, -r1 * r1));
            o.z = fmaf(c, a.z, -r1) * rsqrtf(S);
        }
        {
            c += 1.f; r1 += a.w; r2 = fmaf(a.w, a.w, r2);
            float S = fmaf(EPS * c, c, fmaf(c, r2, -r1 * r1));
            o.w = fmaf(c, a.w, -r1) * rsqrtf(S);
        }
        v[j] = o;
    }

    // 4) direct regs -> gmem store (streaming)
#pragma unroll
    for (int j = 0; j < 4; j++) {
        if (b4 + j < NF4) __stcs(&out[rowbase + b4 + j], v[j]);
    }
}

extern "C" void kernel_launch(void* const* d_in, const int* in_sizes, int n_in,
                              void* d_out, int out_size) {
    const float4* x = (const float4*)d_in[0];
    float4* out = (float4*)d_out;
    const int rows = in_sizes[0] / FRAMES;   // 32*512 = 16384
    cumnorm_kernel<<<rows, T>>>(x, out);
}